// round 12
// baseline (speedup 1.0000x reference)
#include <cuda_runtime.h>
#include <cuda_bf16.h>
#include <math.h>

#define NN 65536        // 256*256
#define NDIM 256
#define DEG_M 16
#define DEG_S 32
#define NB 444          // 148 SMs x 3 blocks -- guaranteed co-resident

// Buffer map (each 256x256 fp32):
//  1..16 : TM_j (Chebyshev basis of Mtilde; TM1 = Mtilde)
//  19..50: TS_j at 18+j (TS1 = Stilde at 19)
//  51    : P
//  60: sq  61: isq  62: tmp
__device__ float g_buf[(size_t)63 * NN];
__device__ float g_params[8];        // [0]=aM+bM [1]=1/(bM-aM) [2]=aS+bS [3]=1/(bS-aS) [4]=aS [5]=bS
__device__ float g_ca[DEG_M + 1];    // sqrt coeffs
__device__ float g_cb[DEG_M + 1];    // isqrt coeffs
__device__ float g_ct[256 * 40];     // per-step x^t coeffs (33 used per step)
__device__ float g_lam[256];         // per-batch lambda_max lower bounds

// grid barrier state (zero-init; kernel leaves it back at zero every run)
__device__ unsigned g_count;
__device__ volatile unsigned g_sense;

// Doubling-tree tasks {Aidx, Bidx, Cidx, mode}: mode -2 => C=2AB-I, >=0 => C=2AB-buf[mode]
__constant__ int4 g_tasks[46] = {
    // TM tree (base 0)
    {1,1,2,-2},                                               // L1
    {2,1,3,1},{2,2,4,-2},                                     // L2
    {3,2,5,1},{3,3,6,-2},{4,3,7,1},{4,4,8,-2},                // L3
    {5,4,9,1},{5,5,10,-2},{6,5,11,1},{6,6,12,-2},             // L4
    {7,6,13,1},{7,7,14,-2},{8,7,15,1},{8,8,16,-2},
    // TS tree (base 15)
    {19,19,20,-2},                                            // L1
    {20,19,21,19},{20,20,22,-2},                              // L2
    {21,20,23,19},{21,21,24,-2},{22,21,25,19},{22,22,26,-2},  // L3
    {23,22,27,19},{23,23,28,-2},{24,23,29,19},{24,24,30,-2},  // L4
    {25,24,31,19},{25,25,32,-2},{26,25,33,19},{26,26,34,-2},
    {27,26,35,19},{27,27,36,-2},{28,27,37,19},{28,28,38,-2},  // L5
    {29,28,39,19},{29,29,40,-2},{30,29,41,19},{30,30,42,-2},
    {31,30,43,19},{31,31,44,-2},{32,31,45,19},{32,32,46,-2},
    {33,32,47,19},{33,33,48,-2},{34,33,49,19},{34,34,50,-2}
};

// ---------------------------------------------------------------------------
// Power iteration: lower bound on lambda_max(f_b). One block per batch.
// ---------------------------------------------------------------------------
__global__ void __launch_bounds__(256) pow_kernel(const float* __restrict__ f) {
    int b = blockIdx.x;
    const float* fb = f + (size_t)b * NN;
    __shared__ float v[256], w[256];
    __shared__ float redB[8], bc[2];
    int tid = threadIdx.x, lane = tid & 31, wp = tid >> 5;
    v[tid] = 1.0f;
    __syncthreads();
    for (int it = 0; it < 100; ++it) {
        for (int rr = wp * 32; rr < wp * 32 + 32; ++rr) {
            const float* row = fb + rr * NDIM;
            float s = 0.f;
            #pragma unroll
            for (int j = 0; j < 8; j++) s += row[lane + 32 * j] * v[lane + 32 * j];
            #pragma unroll
            for (int o = 16; o; o >>= 1) s += __shfl_down_sync(0xffffffffu, s, o);
            if (lane == 0) w[rr] = s;
        }
        __syncthreads();
        float wi = w[tid];
        float p2 = wi * wi;
        #pragma unroll
        for (int o = 16; o; o >>= 1) p2 += __shfl_down_sync(0xffffffffu, p2, o);
        if (lane == 0) redB[wp] = p2;
        __syncthreads();
        if (tid == 0) {
            float s2 = 0.f;
            for (int i = 0; i < 8; i++) s2 += redB[i];
            float nrm = sqrtf(fmaxf(s2, 1e-30f));
            bc[0] = nrm; bc[1] = 1.0f / nrm;
        }
        __syncthreads();
        v[tid] = w[tid] * bc[1];
        __syncthreads();
        if (it == 99 && tid == 0) g_lam[b] = bc[0];
        __syncthreads();
    }
}

// ---------------------------------------------------------------------------
// Intervals + sqrt/isqrt Chebyshev coefficients (1 thread, fp64)
// ---------------------------------------------------------------------------
__global__ void coefA_kernel() {
    const double PI = 3.14159265358979323846;
    double m = 1.0;
    for (int i = 0; i < 256; i++) { double x = (double)g_lam[i]; if (x > m) m = x; }
    double bM = 1.05 * m + 0.01; if (bM < 1.3) bM = 1.3;
    double aM = 0.90;
    double bS = bM / 0.93, aS = 0.93 / bM;
    g_params[0] = (float)(aM + bM); g_params[1] = (float)(1.0 / (bM - aM));
    g_params[2] = (float)(aS + bS); g_params[3] = (float)(1.0 / (bS - aS));
    g_params[4] = (float)aS;        g_params[5] = (float)bS;
    double mid = 0.5 * (aM + bM), half = 0.5 * (bM - aM);
    for (int j = 0; j <= DEG_M; j++) {
        double sa = 0.0, sb = 0.0;
        for (int i = 0; i < 64; i++) {
            double th = (i + 0.5) * PI / 64.0;
            double x = mid + half * cos(th);
            double sq = sqrt(x);
            double cj = cos(j * th);
            sa += cj * sq; sb += cj / sq;
        }
        double sc = ((j == 0) ? 1.0 : 2.0) / 64.0;
        g_ca[j] = (float)(sc * sa);
        g_cb[j] = (float)(sc * sb);
    }
}

// ---------------------------------------------------------------------------
// Per-step Chebyshev coeffs of x^{t_k} on [aS,bS]; block k, 64 nodes, fp64
// ---------------------------------------------------------------------------
__global__ void __launch_bounds__(64) coefT_kernel(const float* __restrict__ wts) {
    const double PI = 3.14159265358979323846;
    int k = blockIdx.x, i = threadIdx.x;
    __shared__ double fv[64];
    double aS = (double)g_params[4], bS = (double)g_params[5];
    double w0 = (double)wts[2 * k], w1 = (double)wts[2 * k + 1];
    double t = 1.0 / (1.0 + exp(w0 - w1));   // softmax(weights)[:,1]
    double th = (i + 0.5) * PI / 64.0;
    double x = 0.5 * (aS + bS) + 0.5 * (bS - aS) * cos(th);
    fv[i] = pow(x, t);
    __syncthreads();
    if (i <= DEG_S) {
        double s = 0.0;
        for (int n = 0; n < 64; n++) {
            double thn = (n + 0.5) * PI / 64.0;
            s += cos((double)i * thn) * fv[n];
        }
        g_ct[k * 40 + i] = (float)((((i == 0) ? 1.0 : 2.0) / 64.0) * s);
    }
}

// ---------------------------------------------------------------------------
// Grid barrier (sense-reversing, single counter). All blocks resident.
// ---------------------------------------------------------------------------
__device__ __forceinline__ void gsync(unsigned& sense) {
    __syncthreads();
    if (threadIdx.x == 0) {
        sense ^= 1u;
        __threadfence();
        if (atomicAdd(&g_count, 1u) == NB - 1u) {
            g_count = 0u;
            __threadfence();
            g_sense = sense;
        } else {
            while (g_sense != sense) { __nanosleep(32); }
            __threadfence();
        }
    }
    __syncthreads();
}

// ---------------------------------------------------------------------------
// 32x32x256 tile matmul core. block = 256 threads, 2x2 outputs each.
// ---------------------------------------------------------------------------
__device__ __forceinline__ void mm_core(const float* __restrict__ A,
                                        const float* __restrict__ B,
                                        int tile, float acc[4],
                                        float As[32][33], float Bs[32][33],
                                        int& r, int& c) {
    int tid = threadIdx.x;
    int lr = tid >> 3, lc = (tid & 7) << 2;
    int tx = tid & 15, ty = tid >> 4;
    int row0 = (tile >> 3) << 5, col0 = (tile & 7) << 5;
    acc[0] = acc[1] = acc[2] = acc[3] = 0.f;
    for (int k0 = 0; k0 < NDIM; k0 += 32) {
        float4 av = *(const float4*)(A + (size_t)(row0 + lr) * NDIM + k0 + lc);
        float4 bv = *(const float4*)(B + (size_t)(k0 + lr) * NDIM + col0 + lc);
        As[lr][lc] = av.x; As[lr][lc + 1] = av.y; As[lr][lc + 2] = av.z; As[lr][lc + 3] = av.w;
        Bs[lr][lc] = bv.x; Bs[lr][lc + 1] = bv.y; Bs[lr][lc + 2] = bv.z; Bs[lr][lc + 3] = bv.w;
        __syncthreads();
        #pragma unroll
        for (int kk = 0; kk < 32; kk++) {
            float b0 = Bs[kk][2 * tx], b1 = Bs[kk][2 * tx + 1];
            float x0 = As[2 * ty][kk], x1 = As[2 * ty + 1][kk];
            acc[0] += x0 * b0; acc[1] += x0 * b1; acc[2] += x1 * b0; acc[3] += x1 * b1;
        }
        __syncthreads();
    }
    r = row0 + 2 * ty; c = col0 + 2 * tx;
}

// Chebyshev doubling-tree phase: tasks [base, base+ntasks), 64 tiles each.
__device__ __forceinline__ void tree_phase(int base, int ntasks,
                                           float As[32][33], float Bs[32][33]) {
    for (int g = blockIdx.x; g < ntasks * 64; g += NB) {
        int4 T = g_tasks[base + (g >> 6)];
        float acc[4]; int r, c;
        mm_core(g_buf + (size_t)T.x * NN, g_buf + (size_t)T.y * NN, g & 63, acc, As, Bs, r, c);
        size_t i00 = (size_t)r * NDIM + c, i10 = i00 + NDIM;
        float* C = g_buf + (size_t)T.z * NN;
        if (T.w == -2) {                        // C = 2AB - I  (r,c even => off-diags are 0)
            float d = (r == c) ? 1.f : 0.f;
            C[i00] = 2.f * acc[0] - d;      C[i00 + 1] = 2.f * acc[1];
            C[i10] = 2.f * acc[2];          C[i10 + 1] = 2.f * acc[3] - d;
        } else {                                // C = 2AB - buf[w]
            const float* D = g_buf + (size_t)T.w * NN;
            C[i00] = 2.f * acc[0] - D[i00];         C[i00 + 1] = 2.f * acc[1] - D[i00 + 1];
            C[i10] = 2.f * acc[2] - D[i10];         C[i10 + 1] = 2.f * acc[3] - D[i10 + 1];
        }
    }
}

// ---------------------------------------------------------------------------
// Persistent fused scan kernel: entire 256-step geodesic recursion.
// ---------------------------------------------------------------------------
__global__ void __launch_bounds__(256, 3) fused_kernel(const float* __restrict__ f,
                                                       float* __restrict__ out) {
    __shared__ float As[32][33];
    __shared__ float Bs[32][33];
    unsigned sense = 0;
    const int tid = threadIdx.x;
    const float c0 = g_params[0], c1 = g_params[1], c2 = g_params[2], c3 = g_params[3];

    // init: TM1 = (2*I - c0*I) * c1   (M0 = I)
    for (int e = blockIdx.x * 256 + tid; e < NN; e += NB * 256) {
        int r = e >> 8, c = e & 255;
        g_buf[NN + e] = (r == c) ? (2.0f - c0) * c1 : 0.0f;
    }
    gsync(sense);

    for (int k = 0; k < 256; ++k) {
        const float* fk = f + (size_t)k * NN;
        float* outk = out + (size_t)k * NN;

        // --- TM Chebyshev tree (deg 16, 4 levels) ---
        tree_phase(0, 1, As, Bs);  gsync(sense);
        tree_phase(1, 2, As, Bs);  gsync(sense);
        tree_phase(3, 4, As, Bs);  gsync(sense);
        tree_phase(7, 8, As, Bs);  gsync(sense);

        // --- sq (60) / isq (61) from TM_1..TM_16 ---
        for (int e = blockIdx.x * 256 + tid; e < NN; e += NB * 256) {
            int r = e >> 8, c = e & 255;
            float s1 = (r == c) ? g_ca[0] : 0.f;
            float s2 = (r == c) ? g_cb[0] : 0.f;
            #pragma unroll
            for (int j = 1; j <= DEG_M; j++) {
                float tv = g_buf[(size_t)j * NN + e];
                s1 += g_ca[j] * tv; s2 += g_cb[j] * tv;
            }
            g_buf[(size_t)60 * NN + e] = s1;
            g_buf[(size_t)61 * NN + e] = s2;
        }
        gsync(sense);

        // --- tmp(62) = isq * fk ---
        for (int g = blockIdx.x; g < 64; g += NB) {
            float acc[4]; int r, c;
            mm_core(g_buf + (size_t)61 * NN, fk, g, acc, As, Bs, r, c);
            size_t i00 = (size_t)r * NDIM + c, i10 = i00 + NDIM;
            float* C = g_buf + (size_t)62 * NN;
            C[i00] = acc[0]; C[i00 + 1] = acc[1]; C[i10] = acc[2]; C[i10 + 1] = acc[3];
        }
        gsync(sense);

        // --- TS1(19) = (2*(tmp*isq) - c2*I) * c3 ---
        for (int g = blockIdx.x; g < 64; g += NB) {
            float acc[4]; int r, c;
            mm_core(g_buf + (size_t)62 * NN, g_buf + (size_t)61 * NN, g, acc, As, Bs, r, c);
            size_t i00 = (size_t)r * NDIM + c, i10 = i00 + NDIM;
            float* C = g_buf + (size_t)19 * NN;
            float d = (r == c) ? c2 : 0.f;
            C[i00]     = (2.f * acc[0] - d) * c3;  C[i00 + 1] = 2.f * acc[1] * c3;
            C[i10]     = 2.f * acc[2] * c3;        C[i10 + 1] = (2.f * acc[3] - d) * c3;
        }
        gsync(sense);

        // --- TS Chebyshev tree (deg 32, 5 levels) ---
        tree_phase(15, 1,  As, Bs); gsync(sense);
        tree_phase(16, 2,  As, Bs); gsync(sense);
        tree_phase(18, 4,  As, Bs); gsync(sense);
        tree_phase(22, 8,  As, Bs); gsync(sense);
        tree_phase(30, 16, As, Bs); gsync(sense);

        // --- P(51) = ct[k][0]*I + sum ct[k][j]*TS_j ---
        {
            const float* ct = g_ct + k * 40;
            for (int e = blockIdx.x * 256 + tid; e < NN; e += NB * 256) {
                int r = e >> 8, c = e & 255;
                float s = (r == c) ? ct[0] : 0.f;
                #pragma unroll
                for (int j = 1; j <= DEG_S; j++)
                    s += ct[j] * g_buf[(size_t)(18 + j) * NN + e];
                g_buf[(size_t)51 * NN + e] = s;
            }
        }
        gsync(sense);

        // --- tmp(62) = sq * P ---
        for (int g = blockIdx.x; g < 64; g += NB) {
            float acc[4]; int r, c;
            mm_core(g_buf + (size_t)60 * NN, g_buf + (size_t)51 * NN, g, acc, As, Bs, r, c);
            size_t i00 = (size_t)r * NDIM + c, i10 = i00 + NDIM;
            float* C = g_buf + (size_t)62 * NN;
            C[i00] = acc[0]; C[i00 + 1] = acc[1]; C[i10] = acc[2]; C[i10 + 1] = acc[3];
        }
        gsync(sense);

        // --- FIN: Mn = tmp * sq -> out[k];  TM1(next) = (2*Mn - c0*I)*c1 ---
        for (int g = blockIdx.x; g < 64; g += NB) {
            float acc[4]; int r, c;
            mm_core(g_buf + (size_t)62 * NN, g_buf + (size_t)60 * NN, g, acc, As, Bs, r, c);
            size_t i00 = (size_t)r * NDIM + c, i10 = i00 + NDIM;
            outk[i00] = acc[0]; outk[i00 + 1] = acc[1];
            outk[i10] = acc[2]; outk[i10 + 1] = acc[3];
            float* T1 = g_buf + NN;
            float d = (r == c) ? c0 : 0.f;
            T1[i00]     = (2.f * acc[0] - d) * c1;  T1[i00 + 1] = 2.f * acc[1] * c1;
            T1[i10]     = 2.f * acc[2] * c1;        T1[i10 + 1] = (2.f * acc[3] - d) * c1;
        }
        gsync(sense);
    }

    // dummy barrier: makes total count even so g_sense/g_count end at 0 for replays
    gsync(sense);
}

// ---------------------------------------------------------------------------
extern "C" void kernel_launch(void* const* d_in, const int* in_sizes, int n_in,
                              void* d_out, int out_size) {
    const float* f = (const float*)d_in[0];        // (256,1,256,256)
    const float* w = (const float*)d_in[1];        // (256,2)
    float* out = (float*)d_out;                    // (256,1,256,256)

    pow_kernel<<<256, 256>>>(f);
    coefA_kernel<<<1, 1>>>();
    coefT_kernel<<<256, 64>>>(w);
    fused_kernel<<<NB, 256>>>(f, out);
}

// round 13
// speedup vs baseline: 1.0680x; 1.0680x over previous
#include <cuda_runtime.h>
#include <cuda_bf16.h>
#include <math.h>

#define NN 65536        // 256*256
#define NDIM 256
#define DEG_I 12        // Chebyshev degree for 1/x  (M inverse)
#define DEG_S 24        // Chebyshev degree for x^t
#define NB 296          // 148 SMs x 2 blocks -- guaranteed co-resident

// Buffer map (each 256x256 fp32):
//  0      : identity matrix (constant after init)
//  1..12  : TM_j  (Chebyshev basis of Mtilde; TM1 = Mtilde)
//  19..42 : TS_j at 18+j (TS1 = Gtilde at 19)
__device__ float g_buf[(size_t)43 * NN];
__device__ float g_params[8];     // [0]=aM+bM [1]=1/(bM-aM) [2]=aS+bS [3]=1/(bS-aS) [4]=aS [5]=bS
__device__ float g_ci[DEG_I + 1]; // 1/x Chebyshev coeffs
__device__ float g_ct[256 * 26];  // per-step x^t coeffs (25 used per step)
__device__ float g_lam[256];      // per-batch lambda_max lower bounds

// grid barrier state (zero-init; kernel leaves it at zero after each run)
__device__ unsigned g_count;
__device__ volatile unsigned g_sense;

// Doubling-tree tasks {Aidx, Bidx, Cidx, mode}: mode -2 => C=2AB-I, >=0 => C=2AB-buf[mode]
__constant__ int4 c_tasks[34] = {
    // TM tree (T_j at buf j), base 0: deg 12
    {1,1,2,-2},                                                // L1
    {2,1,3,1},{2,2,4,-2},                                      // L2
    {3,2,5,1},{3,3,6,-2},{4,3,7,1},{4,4,8,-2},                 // L3
    {5,4,9,1},{5,5,10,-2},{6,5,11,1},{6,6,12,-2},              // L4
    // TS tree (T_j at buf 18+j), base 11: deg 24
    {19,19,20,-2},                                             // L1
    {20,19,21,19},{20,20,22,-2},                               // L2
    {21,20,23,19},{21,21,24,-2},{22,21,25,19},{22,22,26,-2},   // L3
    {23,22,27,19},{23,23,28,-2},{24,23,29,19},{24,24,30,-2},   // L4
    {25,24,31,19},{25,25,32,-2},{26,25,33,19},{26,26,34,-2},
    {27,26,35,19},{27,27,36,-2},{28,27,37,19},{28,28,38,-2},   // L5
    {29,28,39,19},{29,29,40,-2},{30,29,41,19},{30,30,42,-2}
};

// ---------------------------------------------------------------------------
// Power iteration: lower bound on lambda_max(f_b). One block per batch.
// ---------------------------------------------------------------------------
__global__ void __launch_bounds__(256) pow_kernel(const float* __restrict__ f) {
    int b = blockIdx.x;
    const float* fb = f + (size_t)b * NN;
    __shared__ float v[256], w[256];
    __shared__ float redB[8], bc[2];
    int tid = threadIdx.x, lane = tid & 31, wp = tid >> 5;
    v[tid] = 1.0f;
    __syncthreads();
    for (int it = 0; it < 100; ++it) {
        for (int rr = wp * 32; rr < wp * 32 + 32; ++rr) {
            const float* row = fb + rr * NDIM;
            float s = 0.f;
            #pragma unroll
            for (int j = 0; j < 8; j++) s += row[lane + 32 * j] * v[lane + 32 * j];
            #pragma unroll
            for (int o = 16; o; o >>= 1) s += __shfl_down_sync(0xffffffffu, s, o);
            if (lane == 0) w[rr] = s;
        }
        __syncthreads();
        float wi = w[tid];
        float p2 = wi * wi;
        #pragma unroll
        for (int o = 16; o; o >>= 1) p2 += __shfl_down_sync(0xffffffffu, p2, o);
        if (lane == 0) redB[wp] = p2;
        __syncthreads();
        if (tid == 0) {
            float s2 = 0.f;
            for (int i = 0; i < 8; i++) s2 += redB[i];
            float nrm = sqrtf(fmaxf(s2, 1e-30f));
            bc[0] = nrm; bc[1] = 1.0f / nrm;
        }
        __syncthreads();
        v[tid] = w[tid] * bc[1];
        __syncthreads();
        if (it == 99 && tid == 0) g_lam[b] = bc[0];
        __syncthreads();
    }
}

// ---------------------------------------------------------------------------
// Intervals + 1/x Chebyshev coefficients (1 thread, fp64)
// ---------------------------------------------------------------------------
__global__ void coefA_kernel() {
    const double PI = 3.14159265358979323846;
    double m = 1.0;
    for (int i = 0; i < 256; i++) { double x = (double)g_lam[i]; if (x > m) m = x; }
    double bM = 1.05 * m + 0.01; if (bM < 1.3) bM = 1.3;
    double aM = 0.90;
    double bS = bM / 0.93, aS = 0.93 / bM;
    g_params[0] = (float)(aM + bM); g_params[1] = (float)(1.0 / (bM - aM));
    g_params[2] = (float)(aS + bS); g_params[3] = (float)(1.0 / (bS - aS));
    g_params[4] = (float)aS;        g_params[5] = (float)bS;
    double mid = 0.5 * (aM + bM), half = 0.5 * (bM - aM);
    for (int j = 0; j <= DEG_I; j++) {
        double s = 0.0;
        for (int i = 0; i < 64; i++) {
            double th = (i + 0.5) * PI / 64.0;
            double x = mid + half * cos(th);
            s += cos(j * th) / x;
        }
        g_ci[j] = (float)((((j == 0) ? 1.0 : 2.0) / 64.0) * s);
    }
}

// ---------------------------------------------------------------------------
// Per-step Chebyshev coeffs of x^{t_k} on [aS,bS]; block k, 64 nodes, fp64
// ---------------------------------------------------------------------------
__global__ void __launch_bounds__(64) coefT_kernel(const float* __restrict__ wts) {
    const double PI = 3.14159265358979323846;
    int k = blockIdx.x, i = threadIdx.x;
    __shared__ double fv[64];
    double aS = (double)g_params[4], bS = (double)g_params[5];
    double w0 = (double)wts[2 * k], w1 = (double)wts[2 * k + 1];
    double t = 1.0 / (1.0 + exp(w0 - w1));   // softmax(weights)[:,1]
    double th = (i + 0.5) * PI / 64.0;
    double x = 0.5 * (aS + bS) + 0.5 * (bS - aS) * cos(th);
    fv[i] = pow(x, t);
    __syncthreads();
    if (i <= DEG_S) {
        double s = 0.0;
        for (int n = 0; n < 64; n++) {
            double thn = (n + 0.5) * PI / 64.0;
            s += cos((double)i * thn) * fv[n];
        }
        g_ct[k * 26 + i] = (float)((((i == 0) ? 1.0 : 2.0) / 64.0) * s);
    }
}

// ---------------------------------------------------------------------------
// Grid barrier (sense-reversing). All NB blocks resident by construction.
// ---------------------------------------------------------------------------
__device__ __forceinline__ void gsync(unsigned& sense) {
    __syncthreads();
    if (threadIdx.x == 0) {
        sense ^= 1u;
        __threadfence();
        if (atomicAdd(&g_count, 1u) == NB - 1u) {
            g_count = 0u;
            __threadfence();
            g_sense = sense;
        } else {
            while (g_sense != sense) { __nanosleep(32); }
            __threadfence();
        }
    }
    __syncthreads();
}

// ---------------------------------------------------------------------------
// 64x32 tile mm machinery. block = 256 threads, 4x2 outputs per thread.
// A chunk: 64 rows x 32 k (512 float4, 2/thread, transposed store into As[k][row])
// B chunk: 32 k x 32 cols (256 float4, 1/thread, direct store into Bs[k][col])
// ---------------------------------------------------------------------------
__device__ __forceinline__ float4 ldA4(const float* __restrict__ A, int rowBase, int k0, int v) {
    int row = v >> 3, kq = v & 7;
    return *(const float4*)(A + (size_t)(rowBase + row) * NDIM + k0 + 4 * kq);
}
__device__ __forceinline__ float4 ldB4(const float* __restrict__ B, int colBase, int k0, int v) {
    int kr = v >> 3, cq = v & 7;
    return *(const float4*)(B + (size_t)(k0 + kr) * NDIM + colBase + 4 * cq);
}
// Minv combined on the fly: ci0*I + sum_j ci_j * TM_j   (TM_j at buf j)
__device__ __forceinline__ float4 ldA_minv(const float* __restrict__ ciS, int rowBase, int k0, int v) {
    int row = v >> 3, kq = v & 7;
    int r = rowBase + row, cb = k0 + 4 * kq;
    const float* p = g_buf + (size_t)NN + (size_t)r * NDIM + cb;
    float4 s = make_float4(0.f, 0.f, 0.f, 0.f);
    #pragma unroll
    for (int j = 1; j <= DEG_I; j++) {
        float4 tv = *(const float4*)(p + (size_t)(j - 1) * NN);
        float cj = ciS[j];
        s.x += cj * tv.x; s.y += cj * tv.y; s.z += cj * tv.z; s.w += cj * tv.w;
    }
    if (r >= cb && r < cb + 4) ((float*)&s)[r - cb] += ciS[0];
    return s;
}
// P combined on the fly: ct0*I + sum_j ct_j * TS_j   (TS_j at buf 18+j)
__device__ __forceinline__ float4 ldB_P(const float* __restrict__ ctS, int colBase, int k0, int v) {
    int kr = v >> 3, cq = v & 7;
    int rk = k0 + kr, cb = colBase + 4 * cq;
    const float* p = g_buf + (size_t)19 * NN + (size_t)rk * NDIM + cb;
    float4 s = make_float4(0.f, 0.f, 0.f, 0.f);
    #pragma unroll
    for (int j = 1; j <= DEG_S; j++) {
        float4 tv = *(const float4*)(p + (size_t)(j - 1) * NN);
        float cj = ctS[j];
        s.x += cj * tv.x; s.y += cj * tv.y; s.z += cj * tv.z; s.w += cj * tv.w;
    }
    if (rk >= cb && rk < cb + 4) ((float*)&s)[rk - cb] += ctS[0];
    return s;
}
__device__ __forceinline__ void stA(float (*As)[68], int v, float4 a) {
    int row = v >> 3, kq = v & 7;
    As[4 * kq + 0][row] = a.x; As[4 * kq + 1][row] = a.y;
    As[4 * kq + 2][row] = a.z; As[4 * kq + 3][row] = a.w;
}
__device__ __forceinline__ void stB(float (*Bs)[36], int v, float4 b) {
    int kr = v >> 3, cq = v & 7;
    *(float4*)&Bs[kr][4 * cq] = b;
}
__device__ __forceinline__ void inner32(const float (*As)[68], const float (*Bs)[36],
                                        int tx, int ty, float* acc) {
    #pragma unroll
    for (int kk = 0; kk < 32; kk++) {
        float4 av = *(const float4*)&As[kk][4 * ty];
        float2 bv = *(const float2*)&Bs[kk][2 * tx];
        acc[0] += av.x * bv.x; acc[1] += av.x * bv.y;
        acc[2] += av.y * bv.x; acc[3] += av.y * bv.y;
        acc[4] += av.z * bv.x; acc[5] += av.z * bv.y;
        acc[6] += av.w * bv.x; acc[7] += av.w * bv.y;
    }
}

// tree-task tile: C = 2*A*B - D   (D = I or a buffer)
__device__ __forceinline__ void tree_tile(const float* __restrict__ A, const float* __restrict__ B,
                                          const float* __restrict__ D, bool isI,
                                          float* __restrict__ C, int rowBase, int colBase,
                                          float (*As)[68], float (*Bs)[36]) {
    int t = threadIdx.x, tx = t & 15, ty = t >> 4;
    float acc[8];
    #pragma unroll
    for (int i = 0; i < 8; i++) acc[i] = 0.f;
    float4 a0 = ldA4(A, rowBase, 0, t), a1 = ldA4(A, rowBase, 0, t + 256);
    float4 b0 = ldB4(B, colBase, 0, t);
    #pragma unroll
    for (int c8 = 0; c8 < 8; c8++) {
        __syncthreads();
        stA(As, t, a0); stA(As, t + 256, a1); stB(Bs, t, b0);
        __syncthreads();
        if (c8 < 7) {
            int k0 = (c8 + 1) * 32;
            a0 = ldA4(A, rowBase, k0, t); a1 = ldA4(A, rowBase, k0, t + 256);
            b0 = ldB4(B, colBase, k0, t);
        }
        inner32(As, Bs, tx, ty, acc);
    }
    int r0 = rowBase + 4 * ty, c0 = colBase + 2 * tx;
    #pragma unroll
    for (int i = 0; i < 4; i++) {
        int r = r0 + i;
        float d0, d1;
        if (isI) { d0 = (r == c0) ? 1.f : 0.f; d1 = (r == c0 + 1) ? 1.f : 0.f; }
        else     { d0 = D[(size_t)r * NDIM + c0]; d1 = D[(size_t)r * NDIM + c0 + 1]; }
        float2 o; o.x = 2.f * acc[2 * i] - d0; o.y = 2.f * acc[2 * i + 1] - d1;
        *(float2*)(C + (size_t)r * NDIM + c0) = o;
    }
}

__device__ __forceinline__ void tree_level(int base, int ntasks,
                                           float (*As)[68], float (*Bs)[36]) {
    for (int g = blockIdx.x; g < ntasks * 32; g += NB) {
        int4 T = c_tasks[base + (g >> 5)];
        int tile = g & 31;
        int rowBase = (tile >> 3) << 6, colBase = (tile & 7) << 5;
        tree_tile(g_buf + (size_t)T.x * NN, g_buf + (size_t)T.y * NN,
                  (T.w >= 0) ? g_buf + (size_t)T.w * NN : (const float*)0, T.w == -2,
                  g_buf + (size_t)T.z * NN, rowBase, colBase, As, Bs);
    }
}

// Phase B tile: TS1 = (2*(Minv*fk) - c2*I)*c3, Minv combined on the fly
__device__ __forceinline__ void phaseB_tile(const float* __restrict__ fk, const float* __restrict__ ciS,
                                            float c2, float c3, int rowBase, int colBase,
                                            float (*As)[68], float (*Bs)[36]) {
    int t = threadIdx.x, tx = t & 15, ty = t >> 4;
    float acc[8];
    #pragma unroll
    for (int i = 0; i < 8; i++) acc[i] = 0.f;
    float4 a0 = ldA_minv(ciS, rowBase, 0, t), a1 = ldA_minv(ciS, rowBase, 0, t + 256);
    float4 b0 = ldB4(fk, colBase, 0, t);
    #pragma unroll
    for (int c8 = 0; c8 < 8; c8++) {
        __syncthreads();
        stA(As, t, a0); stA(As, t + 256, a1); stB(Bs, t, b0);
        __syncthreads();
        if (c8 < 7) {
            int k0 = (c8 + 1) * 32;
            a0 = ldA_minv(ciS, rowBase, k0, t); a1 = ldA_minv(ciS, rowBase, k0, t + 256);
            b0 = ldB4(fk, colBase, k0, t);
        }
        inner32(As, Bs, tx, ty, acc);
    }
    float* C = g_buf + (size_t)19 * NN;
    int r0 = rowBase + 4 * ty, c0 = colBase + 2 * tx;
    #pragma unroll
    for (int i = 0; i < 4; i++) {
        int r = r0 + i;
        float2 o;
        o.x = (2.f * acc[2 * i]     - ((r == c0    ) ? c2 : 0.f)) * c3;
        o.y = (2.f * acc[2 * i + 1] - ((r == c0 + 1) ? c2 : 0.f)) * c3;
        *(float2*)(C + (size_t)r * NDIM + c0) = o;
    }
}

// Phase D tile: Mn = Mprev * P (P combined on the fly); writes out[k] and next TM1
__device__ __forceinline__ void phaseD_tile(const float* __restrict__ Aprev, const float* __restrict__ ctS,
                                            float c0p, float c1p, float* __restrict__ outk,
                                            int rowBase, int colBase,
                                            float (*As)[68], float (*Bs)[36]) {
    int t = threadIdx.x, tx = t & 15, ty = t >> 4;
    float acc[8];
    #pragma unroll
    for (int i = 0; i < 8; i++) acc[i] = 0.f;
    float4 a0 = ldA4(Aprev, rowBase, 0, t), a1 = ldA4(Aprev, rowBase, 0, t + 256);
    float4 b0 = ldB_P(ctS, colBase, 0, t);
    #pragma unroll
    for (int c8 = 0; c8 < 8; c8++) {
        __syncthreads();
        stA(As, t, a0); stA(As, t + 256, a1); stB(Bs, t, b0);
        __syncthreads();
        if (c8 < 7) {
            int k0 = (c8 + 1) * 32;
            a0 = ldA4(Aprev, rowBase, k0, t); a1 = ldA4(Aprev, rowBase, k0, t + 256);
            b0 = ldB_P(ctS, colBase, k0, t);
        }
        inner32(As, Bs, tx, ty, acc);
    }
    float* T1 = g_buf + (size_t)NN;
    int r0 = rowBase + 4 * ty, c0 = colBase + 2 * tx;
    #pragma unroll
    for (int i = 0; i < 4; i++) {
        int r = r0 + i;
        float v0 = acc[2 * i], v1 = acc[2 * i + 1];
        float2 ov; ov.x = v0; ov.y = v1;
        *(float2*)(outk + (size_t)r * NDIM + c0) = ov;
        float2 o;
        o.x = (2.f * v0 - ((r == c0    ) ? c0p : 0.f)) * c1p;
        o.y = (2.f * v1 - ((r == c0 + 1) ? c0p : 0.f)) * c1p;
        *(float2*)(T1 + (size_t)r * NDIM + c0) = o;
    }
}

// ---------------------------------------------------------------------------
// Persistent fused scan kernel
// ---------------------------------------------------------------------------
__global__ void __launch_bounds__(256, 2) fused_kernel(const float* __restrict__ f,
                                                       float* __restrict__ out) {
    __shared__ float As[32][68];
    __shared__ float Bs[32][36];
    __shared__ float ciS[16];
    __shared__ float ctS[32];
    unsigned sense = 0;
    int t = threadIdx.x;
    if (t < 16) ciS[t] = (t <= DEG_I) ? g_ci[t] : 0.f;
    __syncthreads();
    const float c0 = g_params[0], c1 = g_params[1], c2 = g_params[2], c3 = g_params[3];

    // init: buf0 = I; TM1 = (2I - c0*I)*c1
    for (int e = blockIdx.x * 256 + t; e < NN; e += NB * 256) {
        int r = e >> 8, c = e & 255;
        float d = (r == c) ? 1.f : 0.f;
        g_buf[e] = d;
        g_buf[NN + e] = (r == c) ? (2.f - c0) * c1 : 0.f;
    }
    gsync(sense);

    for (int k = 0; k < 256; ++k) {
        const float* fk = f + (size_t)k * NN;

        // TM Chebyshev tree (deg 12, 4 levels)
        tree_level(0, 1, As, Bs); gsync(sense);
        tree_level(1, 2, As, Bs); gsync(sense);
        tree_level(3, 4, As, Bs); gsync(sense);
        tree_level(7, 4, As, Bs); gsync(sense);

        // Phase B: TS1 = scaled(Minv * fk)
        for (int g = blockIdx.x; g < 32; g += NB) {
            int rowBase = (g >> 3) << 6, colBase = (g & 7) << 5;
            phaseB_tile(fk, ciS, c2, c3, rowBase, colBase, As, Bs);
        }
        gsync(sense);

        // TS Chebyshev tree (deg 24, 5 levels)
        tree_level(11, 1, As, Bs); gsync(sense);
        tree_level(12, 2, As, Bs); gsync(sense);
        tree_level(14, 4, As, Bs); gsync(sense);
        tree_level(18, 8, As, Bs); gsync(sense);
        tree_level(26, 8, As, Bs); gsync(sense);

        // Phase D: Mn = Mprev * P; write out[k] and next TM1
        if (t < 32) ctS[t] = (t <= DEG_S) ? g_ct[k * 26 + t] : 0.f;
        __syncthreads();
        {
            const float* Aprev = (k == 0) ? g_buf : (out + (size_t)(k - 1) * NN);
            float* outk = out + (size_t)k * NN;
            for (int g = blockIdx.x; g < 32; g += NB) {
                int rowBase = (g >> 3) << 6, colBase = (g & 7) << 5;
                phaseD_tile(Aprev, ctS, c0, c1, outk, rowBase, colBase, As, Bs);
            }
        }
        gsync(sense);
    }

    // parity barrier: total gsync count = 1 + 256*11 + 1 = 2818 (even) -> state returns to 0
    gsync(sense);
}

// ---------------------------------------------------------------------------
extern "C" void kernel_launch(void* const* d_in, const int* in_sizes, int n_in,
                              void* d_out, int out_size) {
    const float* f = (const float*)d_in[0];        // (256,1,256,256)
    const float* w = (const float*)d_in[1];        // (256,2)
    float* out = (float*)d_out;                    // (256,1,256,256)

    pow_kernel<<<256, 256>>>(f);
    coefA_kernel<<<1, 1>>>();
    coefT_kernel<<<256, 64>>>(w);
    fused_kernel<<<NB, 256>>>(f, out);
}

// round 14
// speedup vs baseline: 1.3145x; 1.2309x over previous
#include <cuda_runtime.h>
#include <cuda_bf16.h>
#include <math.h>

#define NN 65536        // 256*256
#define NDIM 256
#define DEG_S 24        // Chebyshev degree for x^t / x^-t
#define NB 296          // 148 SMs x 2 blocks, co-resident by construction
#define NGRP 8
#define GRPSZ 37        // 296 = 8 * 37

// Buffer map (each 256x256 fp32):
//  0      : identity
//  1..24  : T_j (Chebyshev basis of Gtilde; T1 = Gtilde)
//  25     : X (Newton scratch)
//  26/27  : Minv ping-pong
__device__ float g_buf[(size_t)28 * NN];
__device__ float g_params[8];     // [2]=aS+bS [3]=1/(bS-aS) [4]=aS [5]=bS
__device__ float g_ct[256 * 26];  // per-step x^t  coeffs (25 used)
__device__ float g_di[256 * 26];  // per-step x^-t coeffs (25 used)
__device__ float g_lam[256];      // per-batch lambda_max lower bounds

// two-level grid barrier state (self-resetting counters)
__device__ unsigned g_cnt[NGRP];
__device__ unsigned g_master;
__device__ volatile unsigned g_sense;

// Doubling-tree tasks {A,B,C,mode}: mode -2 => C=2AB-I, >=0 => C=2AB-buf[mode]
__constant__ int4 c_tasks[23] = {
    {1,1,2,-2},                                                 // L1
    {2,1,3,1},{2,2,4,-2},                                       // L2
    {3,2,5,1},{3,3,6,-2},{4,3,7,1},{4,4,8,-2},                  // L3
    {5,4,9,1},{5,5,10,-2},{6,5,11,1},{6,6,12,-2},               // L4
    {7,6,13,1},{7,7,14,-2},{8,7,15,1},{8,8,16,-2},
    {9,8,17,1},{9,9,18,-2},{10,9,19,1},{10,10,20,-2},           // L5
    {11,10,21,1},{11,11,22,-2},{12,11,23,1},{12,12,24,-2}
};

// ---------------------------------------------------------------------------
// Power iteration: lower bound on lambda_max(f_b). One block per batch.
// ---------------------------------------------------------------------------
__global__ void __launch_bounds__(256) pow_kernel(const float* __restrict__ f) {
    int b = blockIdx.x;
    const float* fb = f + (size_t)b * NN;
    __shared__ float v[256], w[256];
    __shared__ float redB[8], bc[2];
    int tid = threadIdx.x, lane = tid & 31, wp = tid >> 5;
    v[tid] = 1.0f;
    __syncthreads();
    for (int it = 0; it < 100; ++it) {
        for (int rr = wp * 32; rr < wp * 32 + 32; ++rr) {
            const float* row = fb + rr * NDIM;
            float s = 0.f;
            #pragma unroll
            for (int j = 0; j < 8; j++) s += row[lane + 32 * j] * v[lane + 32 * j];
            #pragma unroll
            for (int o = 16; o; o >>= 1) s += __shfl_down_sync(0xffffffffu, s, o);
            if (lane == 0) w[rr] = s;
        }
        __syncthreads();
        float wi = w[tid];
        float p2 = wi * wi;
        #pragma unroll
        for (int o = 16; o; o >>= 1) p2 += __shfl_down_sync(0xffffffffu, p2, o);
        if (lane == 0) redB[wp] = p2;
        __syncthreads();
        if (tid == 0) {
            float s2 = 0.f;
            for (int i = 0; i < 8; i++) s2 += redB[i];
            float nrm = sqrtf(fmaxf(s2, 1e-30f));
            bc[0] = nrm; bc[1] = 1.0f / nrm;
        }
        __syncthreads();
        v[tid] = w[tid] * bc[1];
        __syncthreads();
        if (it == 99 && tid == 0) g_lam[b] = bc[0];
        __syncthreads();
    }
}

// ---------------------------------------------------------------------------
// Interval parameters (1 thread, fp64)
// ---------------------------------------------------------------------------
__global__ void coefA_kernel() {
    double m = 1.0;
    for (int i = 0; i < 256; i++) { double x = (double)g_lam[i]; if (x > m) m = x; }
    double bM = 1.05 * m + 0.01; if (bM < 1.3) bM = 1.3;
    double bS = bM / 0.93, aS = 0.93 / bM;
    g_params[2] = (float)(aS + bS); g_params[3] = (float)(1.0 / (bS - aS));
    g_params[4] = (float)aS;        g_params[5] = (float)bS;
}

// ---------------------------------------------------------------------------
// Per-step Chebyshev coeffs of x^{t_k} AND x^{-t_k} on [aS,bS]; block k, fp64
// ---------------------------------------------------------------------------
__global__ void __launch_bounds__(64) coefT_kernel(const float* __restrict__ wts) {
    const double PI = 3.14159265358979323846;
    int k = blockIdx.x, i = threadIdx.x;
    __shared__ double fp[64], fm[64];
    double aS = (double)g_params[4], bS = (double)g_params[5];
    double w0 = (double)wts[2 * k], w1 = (double)wts[2 * k + 1];
    double t = 1.0 / (1.0 + exp(w0 - w1));   // softmax(weights)[:,1]
    double th = (i + 0.5) * PI / 64.0;
    double x = 0.5 * (aS + bS) + 0.5 * (bS - aS) * cos(th);
    double xp = pow(x, t);
    fp[i] = xp; fm[i] = 1.0 / xp;
    __syncthreads();
    if (i <= DEG_S) {
        double sp = 0.0, sm = 0.0;
        for (int n = 0; n < 64; n++) {
            double thn = (n + 0.5) * PI / 64.0;
            double c = cos((double)i * thn);
            sp += c * fp[n]; sm += c * fm[n];
        }
        double sc = ((i == 0) ? 1.0 : 2.0) / 64.0;
        g_ct[k * 26 + i] = (float)(sc * sp);
        g_di[k * 26 + i] = (float)(sc * sm);
    }
}

// ---------------------------------------------------------------------------
// Two-level grid barrier. Counters self-reset; sense seeded from g_sense.
// ---------------------------------------------------------------------------
__device__ __forceinline__ void gsync(unsigned& sense) {
    __syncthreads();
    if (threadIdx.x == 0) {
        sense ^= 1u;
        __threadfence();
        unsigned grp = blockIdx.x & (NGRP - 1);
        if (atomicAdd(&g_cnt[grp], 1u) == GRPSZ - 1u) {
            g_cnt[grp] = 0u;            // all group members arrived; safe to reset
            __threadfence();
            if (atomicAdd(&g_master, 1u) == NGRP - 1u) {
                g_master = 0u;
                __threadfence();
                g_sense = sense;
            }
        }
        while (g_sense != sense) { __nanosleep(64); }
        __threadfence();
    }
    __syncthreads();
}

// ---------------------------------------------------------------------------
// 64x32 tile mm machinery; block=256 threads, 4x2 outputs per thread.
// ---------------------------------------------------------------------------
__device__ __forceinline__ float4 ldA4(const float* __restrict__ A, int rowBase, int k0, int v) {
    int row = v >> 3, kq = v & 7;
    return *(const float4*)(A + (size_t)(rowBase + row) * NDIM + k0 + 4 * kq);
}
__device__ __forceinline__ float4 ldB4(const float* __restrict__ B, int colBase, int k0, int v) {
    int kr = v >> 3, cq = v & 7;
    return *(const float4*)(B + (size_t)(k0 + kr) * NDIM + colBase + 4 * cq);
}
// P on the fly (B side): ct0*I + sum_j ct_j T_j  (T_j at buf j)
__device__ __forceinline__ float4 ldB_comb(const float* __restrict__ cf, int colBase, int k0, int v) {
    int kr = v >> 3, cq = v & 7;
    int rk = k0 + kr, cb = colBase + 4 * cq;
    const float* p = g_buf + (size_t)NN + (size_t)rk * NDIM + cb;
    float4 s = make_float4(0.f, 0.f, 0.f, 0.f);
    #pragma unroll
    for (int j = 1; j <= DEG_S; j++) {
        float4 tv = *(const float4*)(p + (size_t)(j - 1) * NN);
        float cj = cf[j];
        s.x += cj * tv.x; s.y += cj * tv.y; s.z += cj * tv.z; s.w += cj * tv.w;
    }
    if (rk >= cb && rk < cb + 4) ((float*)&s)[rk - cb] += cf[0];
    return s;
}
// Pinv on the fly (A side)
__device__ __forceinline__ float4 ldA_comb(const float* __restrict__ cf, int rowBase, int k0, int v) {
    int row = v >> 3, kq = v & 7;
    int r = rowBase + row, cb = k0 + 4 * kq;
    const float* p = g_buf + (size_t)NN + (size_t)r * NDIM + cb;
    float4 s = make_float4(0.f, 0.f, 0.f, 0.f);
    #pragma unroll
    for (int j = 1; j <= DEG_S; j++) {
        float4 tv = *(const float4*)(p + (size_t)(j - 1) * NN);
        float cj = cf[j];
        s.x += cj * tv.x; s.y += cj * tv.y; s.z += cj * tv.z; s.w += cj * tv.w;
    }
    if (r >= cb && r < cb + 4) ((float*)&s)[r - cb] += cf[0];
    return s;
}
__device__ __forceinline__ void stA(float (*As)[68], int v, float4 a) {
    int row = v >> 3, kq = v & 7;
    As[4 * kq + 0][row] = a.x; As[4 * kq + 1][row] = a.y;
    As[4 * kq + 2][row] = a.z; As[4 * kq + 3][row] = a.w;
}
__device__ __forceinline__ void stB(float (*Bs)[36], int v, float4 b) {
    int kr = v >> 3, cq = v & 7;
    *(float4*)&Bs[kr][4 * cq] = b;
}
__device__ __forceinline__ void inner32(const float (*As)[68], const float (*Bs)[36],
                                        int tx, int ty, float* acc) {
    #pragma unroll
    for (int kk = 0; kk < 32; kk++) {
        float4 av = *(const float4*)&As[kk][4 * ty];
        float2 bv = *(const float2*)&Bs[kk][2 * tx];
        acc[0] += av.x * bv.x; acc[1] += av.x * bv.y;
        acc[2] += av.y * bv.x; acc[3] += av.y * bv.y;
        acc[4] += av.z * bv.x; acc[5] += av.z * bv.y;
        acc[6] += av.w * bv.x; acc[7] += av.w * bv.y;
    }
}

// Epilogue modes
#define EP_TREE_I  0   // C = 2AB - I
#define EP_TREE_D  1   // C = 2AB - D
#define EP_PLAIN   2   // C = AB
#define EP_SCALE   3   // C = (2AB - c2*I)*c3
#define EP_NEWTON  4   // C = 2D - AB

// Generic tile: A plain or combined, B plain or combined, epilogue by mode.
__device__ __forceinline__ void mm_tile(const float* __restrict__ A, const float* __restrict__ Bp,
                                        const float* __restrict__ combA, const float* __restrict__ combB,
                                        const float* __restrict__ D, float* __restrict__ C,
                                        int mode, float c2, float c3,
                                        int rowBase, int colBase,
                                        float (*As)[68], float (*Bs)[36]) {
    int t = threadIdx.x, tx = t & 15, ty = t >> 4;
    float acc[8];
    #pragma unroll
    for (int i = 0; i < 8; i++) acc[i] = 0.f;
    float4 a0 = combA ? ldA_comb(combA, rowBase, 0, t)       : ldA4(A, rowBase, 0, t);
    float4 a1 = combA ? ldA_comb(combA, rowBase, 0, t + 256) : ldA4(A, rowBase, 0, t + 256);
    float4 b0 = combB ? ldB_comb(combB, colBase, 0, t)       : ldB4(Bp, colBase, 0, t);
    #pragma unroll
    for (int c8 = 0; c8 < 8; c8++) {
        __syncthreads();
        stA(As, t, a0); stA(As, t + 256, a1); stB(Bs, t, b0);
        __syncthreads();
        if (c8 < 7) {
            int k0 = (c8 + 1) * 32;
            a0 = combA ? ldA_comb(combA, rowBase, k0, t)       : ldA4(A, rowBase, k0, t);
            a1 = combA ? ldA_comb(combA, rowBase, k0, t + 256) : ldA4(A, rowBase, k0, t + 256);
            b0 = combB ? ldB_comb(combB, colBase, k0, t)       : ldB4(Bp, colBase, k0, t);
        }
        inner32(As, Bs, tx, ty, acc);
    }
    int r0 = rowBase + 4 * ty, c0 = colBase + 2 * tx;
    #pragma unroll
    for (int i = 0; i < 4; i++) {
        int r = r0 + i;
        size_t idx = (size_t)r * NDIM + c0;
        float2 o;
        if (mode == EP_PLAIN) {
            o.x = acc[2 * i]; o.y = acc[2 * i + 1];
        } else if (mode == EP_TREE_I) {
            o.x = 2.f * acc[2 * i]     - ((r == c0    ) ? 1.f : 0.f);
            o.y = 2.f * acc[2 * i + 1] - ((r == c0 + 1) ? 1.f : 0.f);
        } else if (mode == EP_TREE_D) {
            o.x = 2.f * acc[2 * i]     - D[idx];
            o.y = 2.f * acc[2 * i + 1] - D[idx + 1];
        } else if (mode == EP_SCALE) {
            o.x = (2.f * acc[2 * i]     - ((r == c0    ) ? c2 : 0.f)) * c3;
            o.y = (2.f * acc[2 * i + 1] - ((r == c0 + 1) ? c2 : 0.f)) * c3;
        } else { // EP_NEWTON
            o.x = 2.f * D[idx]     - acc[2 * i];
            o.y = 2.f * D[idx + 1] - acc[2 * i + 1];
        }
        *(float2*)(C + idx) = o;
    }
}

__device__ __forceinline__ void tree_level(int base, int ntasks,
                                           float (*As)[68], float (*Bs)[36]) {
    for (int g = blockIdx.x; g < ntasks * 32; g += NB) {
        int4 T = c_tasks[base + (g >> 5)];
        int tile = g & 31;
        int rowBase = (tile >> 3) << 6, colBase = (tile & 7) << 5;
        mm_tile(g_buf + (size_t)T.x * NN, g_buf + (size_t)T.y * NN, 0, 0,
                (T.w >= 0) ? g_buf + (size_t)T.w * NN : (const float*)0,
                g_buf + (size_t)T.z * NN,
                (T.w == -2) ? EP_TREE_I : EP_TREE_D, 0.f, 0.f,
                rowBase, colBase, As, Bs);
    }
}

// ---------------------------------------------------------------------------
// Persistent fused scan kernel
// ---------------------------------------------------------------------------
__global__ void __launch_bounds__(256, 2) fused_kernel(const float* __restrict__ f,
                                                       float* __restrict__ out) {
    __shared__ float As[32][68];
    __shared__ float Bs[32][36];
    __shared__ float ctS[32];
    __shared__ float diS[32];
    int t = threadIdx.x;
    unsigned sense = g_sense;          // robust across graph replays, any parity
    const float c2 = g_params[2], c3 = g_params[3];

    // init: buf0 = I; Minv(26) = I
    for (int e = blockIdx.x * 256 + t; e < NN; e += NB * 256) {
        int r = e >> 8, c = e & 255;
        float d = (r == c) ? 1.f : 0.f;
        g_buf[e] = d;
        g_buf[(size_t)26 * NN + e] = d;
    }
    gsync(sense);

    int curI = 26;
    for (int k = 0; k < 256; ++k) {
        const float* fk = f + (size_t)k * NN;
        float* outk = out + (size_t)k * NN;
        const float* Minv = g_buf + (size_t)curI * NN;
        int nxtI = 53 - curI;
        float* MinvN = g_buf + (size_t)nxtI * NN;

        // Phase G: T1 = (2*(Minv*fk) - c2*I)*c3
        for (int g = blockIdx.x; g < 32; g += NB) {
            int rowBase = (g >> 3) << 6, colBase = (g & 7) << 5;
            mm_tile(Minv, fk, 0, 0, 0, g_buf + (size_t)NN, EP_SCALE, c2, c3,
                    rowBase, colBase, As, Bs);
        }
        gsync(sense);

        // TS Chebyshev tree (deg 24, 5 levels)
        tree_level(0, 1, As, Bs);  gsync(sense);
        tree_level(1, 2, As, Bs);  gsync(sense);
        tree_level(3, 4, As, Bs);  gsync(sense);
        tree_level(7, 8, As, Bs);  gsync(sense);
        tree_level(15, 8, As, Bs); gsync(sense);

        // Phase D+E (one barrier): D: out[k] = Mprev*P ; E: MinvN = Pinv*Minv
        if (t < 32) {
            ctS[t] = (t <= DEG_S) ? g_ct[k * 26 + t] : 0.f;
            diS[t] = (t <= DEG_S) ? g_di[k * 26 + t] : 0.f;
        }
        __syncthreads();
        {
            const float* Mprev = (k == 0) ? g_buf : (out + (size_t)(k - 1) * NN);
            for (int g = blockIdx.x; g < 64; g += NB) {
                int tile = g & 31;
                int rowBase = (tile >> 3) << 6, colBase = (tile & 7) << 5;
                if (g < 32)
                    mm_tile(Mprev, 0, 0, ctS, 0, outk, EP_PLAIN, 0.f, 0.f,
                            rowBase, colBase, As, Bs);
                else
                    mm_tile(0, Minv, diS, 0, 0, MinvN, EP_PLAIN, 0.f, 0.f,
                            rowBase, colBase, As, Bs);
            }
        }
        gsync(sense);
        curI = nxtI;

        // Newton refresh of Minv every 8 steps: Minv <- Minv*(2I - M*Minv)
        if ((k & 7) == 7) {
            const float* Mc = g_buf + (size_t)curI * NN;
            // N1: X(25) = out[k] * Minv
            for (int g = blockIdx.x; g < 32; g += NB) {
                int rowBase = (g >> 3) << 6, colBase = (g & 7) << 5;
                mm_tile(outk, Mc, 0, 0, 0, g_buf + (size_t)25 * NN, EP_PLAIN, 0.f, 0.f,
                        rowBase, colBase, As, Bs);
            }
            gsync(sense);
            // N2: Minv' = 2*Minv - Minv*X  (write to other buffer)
            int nx2 = 53 - curI;
            for (int g = blockIdx.x; g < 32; g += NB) {
                int rowBase = (g >> 3) << 6, colBase = (g & 7) << 5;
                mm_tile(Mc, g_buf + (size_t)25 * NN, 0, 0, Mc,
                        g_buf + (size_t)nx2 * NN, EP_NEWTON, 0.f, 0.f,
                        rowBase, colBase, As, Bs);
            }
            gsync(sense);
            curI = nx2;
        }
    }
}

// ---------------------------------------------------------------------------
extern "C" void kernel_launch(void* const* d_in, const int* in_sizes, int n_in,
                              void* d_out, int out_size) {
    const float* f = (const float*)d_in[0];        // (256,1,256,256)
    const float* w = (const float*)d_in[1];        // (256,2)
    float* out = (float*)d_out;                    // (256,1,256,256)

    pow_kernel<<<256, 256>>>(f);
    coefA_kernel<<<1, 1>>>();
    coefT_kernel<<<256, 64>>>(w);
    fused_kernel<<<NB, 256>>>(f, out);
}

// round 15
// speedup vs baseline: 1.9312x; 1.4692x over previous
#include <cuda_runtime.h>
#include <cuda_bf16.h>
#include <math.h>

#define NN 65536        // 256*256
#define NDIM 256
#define DEG_S 24        // Chebyshev degree for x^t / x^-t
#define NB 296          // 148 SMs x 2 blocks, co-resident by construction
#define NGRP 8
#define GRPSZ 37        // 296 = 8 * 37

// Buffer map (each 256x256 fp32):
//  0      : identity
//  1..24  : T_j (Chebyshev basis of Gtilde; T1 = Gtilde)
//  25     : X (Newton scratch)
//  26/27  : Minv ping-pong
//  28     : P     29 : Pinv
__device__ float g_buf[(size_t)30 * NN];
__device__ float g_params[8];     // [2]=aS+bS [3]=1/(bS-aS) [4]=aS [5]=bS
__device__ float g_ct[256 * 26];  // per-step x^t  coeffs (25 used)
__device__ float g_di[256 * 26];  // per-step x^-t coeffs (25 used)
__device__ float g_lam[256];      // per-batch lambda_max lower bounds

// two-level grid barrier state (self-resetting counters)
__device__ unsigned g_cnt[NGRP];
__device__ unsigned g_master;
__device__ volatile unsigned g_sense;

// Doubling-tree tasks {A,B,C,mode}: mode -2 => C=2AB-I, >=0 => C=2AB-buf[mode]
__constant__ int4 c_tasks[23] = {
    {1,1,2,-2},                                                 // L1
    {2,1,3,1},{2,2,4,-2},                                       // L2
    {3,2,5,1},{3,3,6,-2},{4,3,7,1},{4,4,8,-2},                  // L3
    {5,4,9,1},{5,5,10,-2},{6,5,11,1},{6,6,12,-2},               // L4
    {7,6,13,1},{7,7,14,-2},{8,7,15,1},{8,8,16,-2},
    {9,8,17,1},{9,9,18,-2},{10,9,19,1},{10,10,20,-2},           // L5
    {11,10,21,1},{11,11,22,-2},{12,11,23,1},{12,12,24,-2}
};

// ---------------------------------------------------------------------------
// Power iteration: lower bound on lambda_max(f_b). One block per batch.
// ---------------------------------------------------------------------------
__global__ void __launch_bounds__(256) pow_kernel(const float* __restrict__ f) {
    int b = blockIdx.x;
    const float* fb = f + (size_t)b * NN;
    __shared__ float v[256], w[256];
    __shared__ float redB[8], bc[2];
    int tid = threadIdx.x, lane = tid & 31, wp = tid >> 5;
    v[tid] = 1.0f;
    __syncthreads();
    for (int it = 0; it < 100; ++it) {
        for (int rr = wp * 32; rr < wp * 32 + 32; ++rr) {
            const float* row = fb + rr * NDIM;
            float s = 0.f;
            #pragma unroll
            for (int j = 0; j < 8; j++) s += row[lane + 32 * j] * v[lane + 32 * j];
            #pragma unroll
            for (int o = 16; o; o >>= 1) s += __shfl_down_sync(0xffffffffu, s, o);
            if (lane == 0) w[rr] = s;
        }
        __syncthreads();
        float wi = w[tid];
        float p2 = wi * wi;
        #pragma unroll
        for (int o = 16; o; o >>= 1) p2 += __shfl_down_sync(0xffffffffu, p2, o);
        if (lane == 0) redB[wp] = p2;
        __syncthreads();
        if (tid == 0) {
            float s2 = 0.f;
            for (int i = 0; i < 8; i++) s2 += redB[i];
            float nrm = sqrtf(fmaxf(s2, 1e-30f));
            bc[0] = nrm; bc[1] = 1.0f / nrm;
        }
        __syncthreads();
        v[tid] = w[tid] * bc[1];
        __syncthreads();
        if (it == 99 && tid == 0) g_lam[b] = bc[0];
        __syncthreads();
    }
}

// ---------------------------------------------------------------------------
// Interval parameters (1 thread, fp64)
// ---------------------------------------------------------------------------
__global__ void coefA_kernel() {
    double m = 1.0;
    for (int i = 0; i < 256; i++) { double x = (double)g_lam[i]; if (x > m) m = x; }
    double bM = 1.05 * m + 0.01; if (bM < 1.3) bM = 1.3;
    double bS = bM / 0.93, aS = 0.93 / bM;
    g_params[2] = (float)(aS + bS); g_params[3] = (float)(1.0 / (bS - aS));
    g_params[4] = (float)aS;        g_params[5] = (float)bS;
}

// ---------------------------------------------------------------------------
// Per-step Chebyshev coeffs of x^{t_k} AND x^{-t_k} on [aS,bS]; block k, fp64
// ---------------------------------------------------------------------------
__global__ void __launch_bounds__(64) coefT_kernel(const float* __restrict__ wts) {
    const double PI = 3.14159265358979323846;
    int k = blockIdx.x, i = threadIdx.x;
    __shared__ double fp[64], fm[64];
    double aS = (double)g_params[4], bS = (double)g_params[5];
    double w0 = (double)wts[2 * k], w1 = (double)wts[2 * k + 1];
    double t = 1.0 / (1.0 + exp(w0 - w1));   // softmax(weights)[:,1]
    double th = (i + 0.5) * PI / 64.0;
    double x = 0.5 * (aS + bS) + 0.5 * (bS - aS) * cos(th);
    double xp = pow(x, t);
    fp[i] = xp; fm[i] = 1.0 / xp;
    __syncthreads();
    if (i <= DEG_S) {
        double sp = 0.0, sm = 0.0;
        for (int n = 0; n < 64; n++) {
            double thn = (n + 0.5) * PI / 64.0;
            double c = cos((double)i * thn);
            sp += c * fp[n]; sm += c * fm[n];
        }
        double sc = ((i == 0) ? 1.0 : 2.0) / 64.0;
        g_ct[k * 26 + i] = (float)(sc * sp);
        g_di[k * 26 + i] = (float)(sc * sm);
    }
}

// ---------------------------------------------------------------------------
// Two-level grid barrier. Counters self-reset; sense seeded from g_sense.
// ---------------------------------------------------------------------------
__device__ __forceinline__ void gsync(unsigned& sense) {
    __syncthreads();
    if (threadIdx.x == 0) {
        sense ^= 1u;
        __threadfence();
        unsigned grp = blockIdx.x & (NGRP - 1);
        if (atomicAdd(&g_cnt[grp], 1u) == GRPSZ - 1u) {
            g_cnt[grp] = 0u;
            __threadfence();
            if (atomicAdd(&g_master, 1u) == NGRP - 1u) {
                g_master = 0u;
                __threadfence();
                g_sense = sense;
            }
        }
        while (g_sense != sense) { __nanosleep(64); }
        __threadfence();
    }
    __syncthreads();
}

// ---------------------------------------------------------------------------
// 64x32 tile mm machinery; block=256 threads, 4x2 outputs per thread.
// ---------------------------------------------------------------------------
__device__ __forceinline__ float4 ldA4(const float* __restrict__ A, int rowBase, int k0, int v) {
    int row = v >> 3, kq = v & 7;
    return *(const float4*)(A + (size_t)(rowBase + row) * NDIM + k0 + 4 * kq);
}
__device__ __forceinline__ float4 ldB4(const float* __restrict__ B, int colBase, int k0, int v) {
    int kr = v >> 3, cq = v & 7;
    return *(const float4*)(B + (size_t)(k0 + kr) * NDIM + colBase + 4 * cq);
}
__device__ __forceinline__ void stA(float (*As)[68], int v, float4 a) {
    int row = v >> 3, kq = v & 7;
    As[4 * kq + 0][row] = a.x; As[4 * kq + 1][row] = a.y;
    As[4 * kq + 2][row] = a.z; As[4 * kq + 3][row] = a.w;
}
__device__ __forceinline__ void stB(float (*Bs)[36], int v, float4 b) {
    int kr = v >> 3, cq = v & 7;
    *(float4*)&Bs[kr][4 * cq] = b;
}
__device__ __forceinline__ void inner32(const float (*As)[68], const float (*Bs)[36],
                                        int tx, int ty, float* acc) {
    #pragma unroll
    for (int kk = 0; kk < 32; kk++) {
        float4 av = *(const float4*)&As[kk][4 * ty];
        float2 bv = *(const float2*)&Bs[kk][2 * tx];
        acc[0] += av.x * bv.x; acc[1] += av.x * bv.y;
        acc[2] += av.y * bv.x; acc[3] += av.y * bv.y;
        acc[4] += av.z * bv.x; acc[5] += av.z * bv.y;
        acc[6] += av.w * bv.x; acc[7] += av.w * bv.y;
    }
}

// Epilogue modes
#define EP_TREE_I  0   // C = 2AB - I
#define EP_TREE_D  1   // C = 2AB - D
#define EP_PLAIN   2   // C = AB
#define EP_SCALE   3   // C = (2AB - c2*I)*c3
#define EP_NEWTON  4   // C = 2D - AB

__device__ __forceinline__ void mm_tile(const float* __restrict__ A, const float* __restrict__ B,
                                        const float* __restrict__ D, float* __restrict__ C,
                                        int mode, float c2, float c3,
                                        int rowBase, int colBase,
                                        float (*As)[68], float (*Bs)[36]) {
    int t = threadIdx.x, tx = t & 15, ty = t >> 4;
    float acc[8];
    #pragma unroll
    for (int i = 0; i < 8; i++) acc[i] = 0.f;
    float4 a0 = ldA4(A, rowBase, 0, t), a1 = ldA4(A, rowBase, 0, t + 256);
    float4 b0 = ldB4(B, colBase, 0, t);
    #pragma unroll
    for (int c8 = 0; c8 < 8; c8++) {
        __syncthreads();
        stA(As, t, a0); stA(As, t + 256, a1); stB(Bs, t, b0);
        __syncthreads();
        if (c8 < 7) {
            int k0 = (c8 + 1) * 32;
            a0 = ldA4(A, rowBase, k0, t); a1 = ldA4(A, rowBase, k0, t + 256);
            b0 = ldB4(B, colBase, k0, t);
        }
        inner32(As, Bs, tx, ty, acc);
    }
    int r0 = rowBase + 4 * ty, c0 = colBase + 2 * tx;
    #pragma unroll
    for (int i = 0; i < 4; i++) {
        int r = r0 + i;
        size_t idx = (size_t)r * NDIM + c0;
        float2 o;
        if (mode == EP_PLAIN) {
            o.x = acc[2 * i]; o.y = acc[2 * i + 1];
        } else if (mode == EP_TREE_I) {
            o.x = 2.f * acc[2 * i]     - ((r == c0    ) ? 1.f : 0.f);
            o.y = 2.f * acc[2 * i + 1] - ((r == c0 + 1) ? 1.f : 0.f);
        } else if (mode == EP_TREE_D) {
            o.x = 2.f * acc[2 * i]     - D[idx];
            o.y = 2.f * acc[2 * i + 1] - D[idx + 1];
        } else if (mode == EP_SCALE) {
            o.x = (2.f * acc[2 * i]     - ((r == c0    ) ? c2 : 0.f)) * c3;
            o.y = (2.f * acc[2 * i + 1] - ((r == c0 + 1) ? c2 : 0.f)) * c3;
        } else { // EP_NEWTON
            o.x = 2.f * D[idx]     - acc[2 * i];
            o.y = 2.f * D[idx + 1] - acc[2 * i + 1];
        }
        *(float2*)(C + idx) = o;
    }
}

__device__ __forceinline__ void tree_level(int base, int ntasks,
                                           float (*As)[68], float (*Bs)[36]) {
    for (int g = blockIdx.x; g < ntasks * 32; g += NB) {
        int4 T = c_tasks[base + (g >> 5)];
        int tile = g & 31;
        int rowBase = (tile >> 3) << 6, colBase = (tile & 7) << 5;
        mm_tile(g_buf + (size_t)T.x * NN, g_buf + (size_t)T.y * NN,
                (T.w >= 0) ? g_buf + (size_t)T.w * NN : (const float*)0,
                g_buf + (size_t)T.z * NN,
                (T.w == -2) ? EP_TREE_I : EP_TREE_D, 0.f, 0.f,
                rowBase, colBase, As, Bs);
    }
}

// ---------------------------------------------------------------------------
// Persistent fused scan kernel
// ---------------------------------------------------------------------------
__global__ void __launch_bounds__(256, 2) fused_kernel(const float* __restrict__ f,
                                                       float* __restrict__ out) {
    __shared__ float As[32][68];
    __shared__ float Bs[32][36];
    __shared__ float ctS[32];
    __shared__ float diS[32];
    int t = threadIdx.x;
    unsigned sense = g_sense;          // robust across graph replays, any parity
    const float c2 = g_params[2], c3 = g_params[3];

    // init: buf0 = I; Minv(26) = I
    for (int e = blockIdx.x * 256 + t; e < NN; e += NB * 256) {
        int r = e >> 8, c = e & 255;
        float d = (r == c) ? 1.f : 0.f;
        g_buf[e] = d;
        g_buf[(size_t)26 * NN + e] = d;
    }
    gsync(sense);

    int curI = 26;
    for (int k = 0; k < 256; ++k) {
        const float* fk = f + (size_t)k * NN;
        float* outk = out + (size_t)k * NN;
        const float* Minv = g_buf + (size_t)curI * NN;
        int nxtI = 53 - curI;
        float* MinvN = g_buf + (size_t)nxtI * NN;

        // stage per-step coefficients into smem (used by combine phase)
        if (t < 32) {
            ctS[t] = (t <= DEG_S) ? g_ct[k * 26 + t] : 0.f;
            diS[t] = (t <= DEG_S) ? g_di[k * 26 + t] : 0.f;
        }

        // Phase G: T1 = (2*(Minv*fk) - c2*I)*c3
        for (int g = blockIdx.x; g < 32; g += NB) {
            int rowBase = (g >> 3) << 6, colBase = (g & 7) << 5;
            mm_tile(Minv, fk, 0, g_buf + (size_t)NN, EP_SCALE, c2, c3,
                    rowBase, colBase, As, Bs);
        }
        gsync(sense);

        // TS Chebyshev tree (deg 24, 5 levels)
        tree_level(0, 1, As, Bs);  gsync(sense);
        tree_level(1, 2, As, Bs);  gsync(sense);
        tree_level(3, 4, As, Bs);  gsync(sense);
        tree_level(7, 8, As, Bs);  gsync(sense);
        tree_level(15, 8, As, Bs); gsync(sense);

        // Phase C: materialize P(28) and Pinv(29) elementwise (each T_j read once)
        {
            float* P  = g_buf + (size_t)28 * NN;
            float* Pi = g_buf + (size_t)29 * NN;
            for (int e = blockIdx.x * 256 + t; e < NN; e += NB * 256) {
                int r = e >> 8, c = e & 255;
                float sp = (r == c) ? ctS[0] : 0.f;
                float si = (r == c) ? diS[0] : 0.f;
                #pragma unroll
                for (int j = 1; j <= DEG_S; j++) {
                    float tv = g_buf[(size_t)j * NN + e];
                    sp += ctS[j] * tv;
                    si += diS[j] * tv;
                }
                P[e] = sp; Pi[e] = si;
            }
        }
        gsync(sense);

        // Phase D+E (one barrier): out[k] = Mprev*P ; MinvN = Pinv*Minv
        {
            const float* Mprev = (k == 0) ? g_buf : (out + (size_t)(k - 1) * NN);
            const float* P  = g_buf + (size_t)28 * NN;
            const float* Pi = g_buf + (size_t)29 * NN;
            for (int g = blockIdx.x; g < 64; g += NB) {
                int tile = g & 31;
                int rowBase = (tile >> 3) << 6, colBase = (tile & 7) << 5;
                if (g < 32)
                    mm_tile(Mprev, P, 0, outk, EP_PLAIN, 0.f, 0.f,
                            rowBase, colBase, As, Bs);
                else
                    mm_tile(Pi, Minv, 0, MinvN, EP_PLAIN, 0.f, 0.f,
                            rowBase, colBase, As, Bs);
            }
        }
        gsync(sense);
        curI = nxtI;

        // Newton refresh of Minv every 8 steps: Minv <- Minv*(2I - M*Minv)
        if ((k & 7) == 7) {
            const float* Mc = g_buf + (size_t)curI * NN;
            for (int g = blockIdx.x; g < 32; g += NB) {
                int rowBase = (g >> 3) << 6, colBase = (g & 7) << 5;
                mm_tile(outk, Mc, 0, g_buf + (size_t)25 * NN, EP_PLAIN, 0.f, 0.f,
                        rowBase, colBase, As, Bs);
            }
            gsync(sense);
            int nx2 = 53 - curI;
            for (int g = blockIdx.x; g < 32; g += NB) {
                int rowBase = (g >> 3) << 6, colBase = (g & 7) << 5;
                mm_tile(Mc, g_buf + (size_t)25 * NN, Mc,
                        g_buf + (size_t)nx2 * NN, EP_NEWTON, 0.f, 0.f,
                        rowBase, colBase, As, Bs);
            }
            gsync(sense);
            curI = nx2;
        }
    }
}

// ---------------------------------------------------------------------------
extern "C" void kernel_launch(void* const* d_in, const int* in_sizes, int n_in,
                              void* d_out, int out_size) {
    const float* f = (const float*)d_in[0];        // (256,1,256,256)
    const float* w = (const float*)d_in[1];        // (256,2)
    float* out = (float*)d_out;                    // (256,1,256,256)

    pow_kernel<<<256, 256>>>(f);
    coefA_kernel<<<1, 1>>>();
    coefT_kernel<<<256, 64>>>(w);
    fused_kernel<<<NB, 256>>>(f, out);
}